// round 2
// baseline (speedup 1.0000x reference)
#include <cuda_runtime.h>

#define D    64
#define KC   512
#define TPB  256
#define RPT  2
#define LDW  68   // padded SMEM row stride (floats): 16B-aligned, breaks 32-way conflicts

__device__ double g_loss_sum;

__global__ void vq_init_kernel() { g_loss_sum = 0.0; }

__global__ void __launch_bounds__(TPB, 1)
vq_main_kernel(const float* __restrict__ x, const float* __restrict__ emb,
               float* __restrict__ out_q, float* __restrict__ out_idx, int n_rows)
{
    extern __shared__ float smem[];
    float* sw = smem;             // [KC][LDW] transposed codebook
    float* hw = smem + KC * LDW;  // [KC] 0.5*||w_k||^2

    // Load + transpose embeddings (global layout [D][K]) — coalesced global reads.
    for (int i = threadIdx.x; i < D * KC; i += TPB) {
        int d = i >> 9;          // i / 512
        int k = i & (KC - 1);    // i % 512
        sw[k * LDW + d] = emb[i];
    }
    __syncthreads();
    for (int k = threadIdx.x; k < KC; k += TPB) {
        const float* w = sw + k * LDW;
        float s = 0.f;
        #pragma unroll
        for (int d = 0; d < D; d++) s += w[d] * w[d];
        hw[k] = 0.5f * s;
    }
    __syncthreads();

    const int r0 = blockIdx.x * (TPB * RPT) + threadIdx.x;
    const int r1 = r0 + TPB;
    const bool v0 = r0 < n_rows;
    const bool v1 = r1 < n_rows;

    float x0[D], x1[D];
    if (v0) {
        const float4* p = (const float4*)(x + (size_t)r0 * D);
        #pragma unroll
        for (int j = 0; j < D / 4; j++) {
            float4 t = p[j];
            x0[4*j] = t.x; x0[4*j+1] = t.y; x0[4*j+2] = t.z; x0[4*j+3] = t.w;
        }
    } else {
        #pragma unroll
        for (int j = 0; j < D; j++) x0[j] = 0.f;
    }
    if (v1) {
        const float4* p = (const float4*)(x + (size_t)r1 * D);
        #pragma unroll
        for (int j = 0; j < D / 4; j++) {
            float4 t = p[j];
            x1[4*j] = t.x; x1[4*j+1] = t.y; x1[4*j+2] = t.z; x1[4*j+3] = t.w;
        }
    } else {
        #pragma unroll
        for (int j = 0; j < D; j++) x1[j] = 0.f;
    }

    float best0 = -3.402823466e38f, best1 = -3.402823466e38f;
    int   b0 = 0, b1 = 0;

    #pragma unroll 1
    for (int k = 0; k < KC; k++) {
        const float4* wr = (const float4*)(sw + k * LDW);
        float a0 = 0.f, c0 = 0.f, a1 = 0.f, c1 = 0.f;  // 2 partial chains per row
        #pragma unroll
        for (int j = 0; j < 16; j += 2) {
            float4 w  = wr[j];
            float4 w2 = wr[j + 1];
            a0 = fmaf(x0[4*j+3], w.w,  fmaf(x0[4*j+2], w.z,  fmaf(x0[4*j+1], w.y,  fmaf(x0[4*j+0], w.x,  a0))));
            c0 = fmaf(x0[4*j+7], w2.w, fmaf(x0[4*j+6], w2.z, fmaf(x0[4*j+5], w2.y, fmaf(x0[4*j+4], w2.x, c0))));
            a1 = fmaf(x1[4*j+3], w.w,  fmaf(x1[4*j+2], w.z,  fmaf(x1[4*j+1], w.y,  fmaf(x1[4*j+0], w.x,  a1))));
            c1 = fmaf(x1[4*j+7], w2.w, fmaf(x1[4*j+6], w2.z, fmaf(x1[4*j+5], w2.y, fmaf(x1[4*j+4], w2.x, c1))));
        }
        float hwk = hw[k];
        float s0 = (a0 + c0) - hwk;
        float s1 = (a1 + c1) - hwk;
        if (s0 > best0) { best0 = s0; b0 = k; }   // strict > keeps first index (argmin semantics)
        if (s1 > best1) { best1 = s1; b1 = k; }
    }

    // Epilogue: gather winning code, write quantized + index, accumulate loss.
    double lsum = 0.0;
    if (v0) {
        const float* w = sw + b0 * LDW;
        float4* q = (float4*)(out_q + (size_t)r0 * D);
        #pragma unroll
        for (int j = 0; j < 16; j++) {
            float4 t;
            t.x = w[4*j]; t.y = w[4*j+1]; t.z = w[4*j+2]; t.w = w[4*j+3];
            q[j] = t;
            float d0 = t.x - x0[4*j],   d1 = t.y - x0[4*j+1];
            float d2 = t.z - x0[4*j+2], d3 = t.w - x0[4*j+3];
            lsum += (double)(d0*d0 + d1*d1 + d2*d2 + d3*d3);
        }
        out_idx[r0] = (float)b0;
    }
    if (v1) {
        const float* w = sw + b1 * LDW;
        float4* q = (float4*)(out_q + (size_t)r1 * D);
        #pragma unroll
        for (int j = 0; j < 16; j++) {
            float4 t;
            t.x = w[4*j]; t.y = w[4*j+1]; t.z = w[4*j+2]; t.w = w[4*j+3];
            q[j] = t;
            float d0 = t.x - x1[4*j],   d1 = t.y - x1[4*j+1];
            float d2 = t.z - x1[4*j+2], d3 = t.w - x1[4*j+3];
            lsum += (double)(d0*d0 + d1*d1 + d2*d2 + d3*d3);
        }
        out_idx[r1] = (float)b1;
    }

    // Block reduction of loss partials -> one atomic per block.
    unsigned mask = 0xffffffffu;
    #pragma unroll
    for (int off = 16; off; off >>= 1) lsum += __shfl_down_sync(mask, lsum, off);
    __shared__ double red[TPB / 32];
    int wid  = threadIdx.x >> 5;
    int lane = threadIdx.x & 31;
    if (lane == 0) red[wid] = lsum;
    __syncthreads();
    if (wid == 0) {
        double v = (lane < TPB / 32) ? red[lane] : 0.0;
        #pragma unroll
        for (int off = 4; off; off >>= 1) v += __shfl_down_sync(mask, v, off);
        if (lane == 0) atomicAdd(&g_loss_sum, v);
    }
}

__global__ void vq_fin_kernel(float* __restrict__ out_loss, double inv_count)
{
    // loss = mean(sq) + 0.25*mean(sq) = 1.25 * mean(sq)  (stop_gradient is identity on values)
    *out_loss = (float)(1.25 * g_loss_sum * inv_count);
}

extern "C" void kernel_launch(void* const* d_in, const int* in_sizes, int n_in,
                              void* d_out, int out_size)
{
    const float* x   = (const float*)d_in[0];   // [N, 64] flattened inputs
    const float* emb = (const float*)d_in[1];   // [64, 512]

    const int n_rows = in_sizes[0] / D;         // 65536
    float* out      = (float*)d_out;
    float* out_q    = out;                               // N*D quantized_st
    float* out_idx  = out + (size_t)n_rows * D;          // N indices (as f32)
    float* out_loss = out_idx + n_rows;                  // 1 scalar loss

    size_t smem_bytes = (size_t)(KC * LDW + KC) * sizeof(float);
    cudaFuncSetAttribute(vq_main_kernel,
                         cudaFuncAttributeMaxDynamicSharedMemorySize,
                         (int)smem_bytes);

    int grid = (n_rows + TPB * RPT - 1) / (TPB * RPT);   // 128 blocks

    vq_init_kernel<<<1, 1>>>();
    vq_main_kernel<<<grid, TPB, smem_bytes>>>(x, emb, out_q, out_idx, n_rows);
    vq_fin_kernel<<<1, 1>>>(out_loss, 1.0 / ((double)n_rows * (double)D));
}

// round 3
// speedup vs baseline: 1.2121x; 1.2121x over previous
#include <cuda_runtime.h>

#define D    64
#define KC   512
#define TPB  256
#define BN   128     // rows per block
#define BC   128     // codes per tile
#define XS   130     // xs row stride (floats): even (8B-align for paired loads), 130%32=2 (conflict-light transpose)

typedef unsigned long long ull;

__device__ double g_loss_sum;

__global__ void vq_init_kernel() { g_loss_sum = 0.0; }

__device__ __forceinline__ ull ffma2(ull a, ull b, ull c) {
    ull d;
    asm("fma.rn.f32x2 %0, %1, %2, %3;" : "=l"(d) : "l"(a), "l"(b), "l"(c));
    return d;
}
__device__ __forceinline__ ull pack2(float w) {
    ull d;
    asm("mov.b64 %0, {%1, %1};" : "=l"(d) : "r"(__float_as_uint(w)));
    return d;
}
__device__ __forceinline__ float2 unpack2(ull p) {
    float2 f;
    asm("mov.b64 {%0, %1}, %2;" : "=f"(f.x), "=f"(f.y) : "l"(p));
    return f;
}

__global__ void __launch_bounds__(TPB, 1)
vq_main_kernel(const float* __restrict__ x, const float* __restrict__ emb,
               float* __restrict__ out_q, float* __restrict__ out_idx, int n_rows)
{
    extern __shared__ float smem[];
    float*  ws    = smem;                    // [64][512] codebook, same layout as emb
    float*  xs    = ws + D * KC;             // [64][XS] transposed x rows
    float*  hww   = xs + D * XS;             // [512] 0.5*||w_k||^2
    int*    sbidx = (int*)(hww + KC);        // [BN] winning code per row
    double* sred  = (double*)(sbidx + BN);   // [8] loss reduction scratch

    const int t = threadIdx.x;
    const int rowbase = blockIdx.x * BN;

    // ---- Load codebook (direct copy, coalesced) ----
    {
        const float4* e4 = (const float4*)emb;
        float4* w4 = (float4*)ws;
        #pragma unroll
        for (int i = t; i < D * KC / 4; i += TPB) w4[i] = e4[i];
    }
    // ---- Load x rows, transposed into xs[d][row] ----
    #pragma unroll
    for (int i = t; i < BN * D / 4; i += TPB) {
        int row = i >> 4;              // 16 float4 per row
        int j   = i & 15;
        int d0  = j << 2;
        int gr  = rowbase + row;
        float4 v = make_float4(0.f, 0.f, 0.f, 0.f);
        if (gr < n_rows) v = ((const float4*)x)[(size_t)gr * (D / 4) + j];
        xs[(d0 + 0) * XS + row] = v.x;
        xs[(d0 + 1) * XS + row] = v.y;
        xs[(d0 + 2) * XS + row] = v.z;
        xs[(d0 + 3) * XS + row] = v.w;
    }
    __syncthreads();
    // ---- 0.5*||w||^2 per code ----
    for (int k = t; k < KC; k += TPB) {
        float s = 0.f;
        #pragma unroll
        for (int d = 0; d < D; d++) { float w = ws[d * KC + k]; s = fmaf(w, w, s); }
        hww[k] = 0.5f * s;
    }
    __syncthreads();

    // ---- Main: 8 rows x 8 codes per thread, packed f32x2 FMA ----
    const int tx = t & 15;         // code group
    const int ty = t >> 4;         // row group
    const int r0 = ty * 8;

    float best[8];
    int   bidr[8];
    #pragma unroll
    for (int r = 0; r < 8; r++) { best[r] = -3.402823466e38f; bidr[r] = 0; }

    const float* xp_base = xs + r0;

    #pragma unroll 1
    for (int tile = 0; tile < 4; tile++) {
        const int c0 = tile * BC + tx * 8;
        const float* wp_base = ws + c0;

        ull acc[4][8];
        #pragma unroll
        for (int m = 0; m < 4; m++)
            #pragma unroll
            for (int c = 0; c < 8; c++) acc[m][c] = 0ull;

        #pragma unroll 4
        for (int d = 0; d < D; d++) {
            ull xp[4];
            #pragma unroll
            for (int m = 0; m < 4; m++)
                xp[m] = *(const ull*)(xp_base + d * XS + 2 * m);   // rows (r0+2m, r0+2m+1) packed

            float4 w0 = *(const float4*)(wp_base + d * KC);
            float4 w1 = *(const float4*)(wp_base + d * KC + 4);
            ull wq[8];
            wq[0] = pack2(w0.x); wq[1] = pack2(w0.y); wq[2] = pack2(w0.z); wq[3] = pack2(w0.w);
            wq[4] = pack2(w1.x); wq[5] = pack2(w1.y); wq[6] = pack2(w1.z); wq[7] = pack2(w1.w);

            #pragma unroll
            for (int m = 0; m < 4; m++)
                #pragma unroll
                for (int c = 0; c < 8; c++)
                    acc[m][c] = ffma2(xp[m], wq[c], acc[m][c]);
        }

        float4 h0 = *(const float4*)(hww + c0);
        float4 h1 = *(const float4*)(hww + c0 + 4);
        float hv[8] = {h0.x, h0.y, h0.z, h0.w, h1.x, h1.y, h1.z, h1.w};

        #pragma unroll
        for (int c = 0; c < 8; c++) {
            const int cg = c0 + c;
            #pragma unroll
            for (int m = 0; m < 4; m++) {
                float2 s2 = unpack2(acc[m][c]);
                float s_lo = s2.x - hv[c];
                float s_hi = s2.y - hv[c];
                if (s_lo > best[2 * m])     { best[2 * m]     = s_lo; bidr[2 * m]     = cg; }
                if (s_hi > best[2 * m + 1]) { best[2 * m + 1] = s_hi; bidr[2 * m + 1] = cg; }
            }
        }
    }

    // ---- Cross-lane argmax reduction over the 16 code-group lanes (width 16) ----
    #pragma unroll
    for (int r = 0; r < 8; r++) {
        float v  = best[r];
        int   bi = bidr[r];
        #pragma unroll
        for (int off = 8; off; off >>= 1) {
            float ov = __shfl_xor_sync(0xffffffffu, v,  off, 16);
            int   oi = __shfl_xor_sync(0xffffffffu, bi, off, 16);
            if (ov > v || (ov == v && oi < bi)) { v = ov; bi = oi; }
        }
        if (tx == 0) sbidx[r0 + r] = bi;
    }
    __syncthreads();

    // ---- Epilogue: gather winning code, write quantized + loss ----
    double lsum = 0.0;
    {
        const int row  = t >> 1;         // 2 threads per row
        const int half = t & 1;
        const int grow = rowbase + row;
        if (grow < n_rows) {
            const int k     = sbidx[row];
            const int dbase = half * 32;
            float4* qo = (float4*)(out_q + (size_t)grow * D + dbase);
            #pragma unroll
            for (int j = 0; j < 8; j++) {
                const int d = dbase + j * 4;
                float q0 = ws[(d + 0) * KC + k];
                float q1 = ws[(d + 1) * KC + k];
                float q2 = ws[(d + 2) * KC + k];
                float q3 = ws[(d + 3) * KC + k];
                float a0 = xs[(d + 0) * XS + row];
                float a1 = xs[(d + 1) * XS + row];
                float a2 = xs[(d + 2) * XS + row];
                float a3 = xs[(d + 3) * XS + row];
                qo[j] = make_float4(q0, q1, q2, q3);
                float e0 = q0 - a0, e1 = q1 - a1, e2 = q2 - a2, e3 = q3 - a3;
                lsum += (double)(e0 * e0 + e1 * e1 + e2 * e2 + e3 * e3);
            }
        }
        if (t < BN && rowbase + t < n_rows) out_idx[rowbase + t] = (float)sbidx[t];
    }

    // ---- Block loss reduction -> one atomic ----
    const unsigned mask = 0xffffffffu;
    #pragma unroll
    for (int off = 16; off; off >>= 1) lsum += __shfl_down_sync(mask, lsum, off);
    const int wid  = t >> 5;
    const int lane = t & 31;
    if (lane == 0) sred[wid] = lsum;
    __syncthreads();
    if (wid == 0) {
        double v = (lane < TPB / 32) ? sred[lane] : 0.0;
        #pragma unroll
        for (int off = 4; off; off >>= 1) v += __shfl_down_sync(mask, v, off);
        if (lane == 0) atomicAdd(&g_loss_sum, v);
    }
}

__global__ void vq_fin_kernel(float* __restrict__ out_loss, double inv_count)
{
    *out_loss = (float)(1.25 * g_loss_sum * inv_count);
}

extern "C" void kernel_launch(void* const* d_in, const int* in_sizes, int n_in,
                              void* d_out, int out_size)
{
    const float* x   = (const float*)d_in[0];   // [N, 64]
    const float* emb = (const float*)d_in[1];   // [64, 512]

    const int n_rows = in_sizes[0] / D;
    float* out      = (float*)d_out;
    float* out_q    = out;
    float* out_idx  = out + (size_t)n_rows * D;
    float* out_loss = out_idx + n_rows;

    size_t smem_bytes = (size_t)(D * KC + D * XS + KC) * sizeof(float)
                      + BN * sizeof(int) + 8 * sizeof(double);
    cudaFuncSetAttribute(vq_main_kernel,
                         cudaFuncAttributeMaxDynamicSharedMemorySize,
                         (int)smem_bytes);

    int grid = (n_rows + BN - 1) / BN;   // 512

    vq_init_kernel<<<1, 1>>>();
    vq_main_kernel<<<grid, TPB, smem_bytes>>>(x, emb, out_q, out_idx, n_rows);
    vq_fin_kernel<<<1, 1>>>(out_loss, 1.0 / ((double)n_rows * (double)D));
}

// round 5
// speedup vs baseline: 2.2841x; 1.8844x over previous
#include <cuda_runtime.h>
#include <cuda_fp16.h>
#include <cstdint>

#define KC   512
#define DD   64
#define TPB  256
#define BN   128
#define LDA  72      // fp16 elems per smem row (144B: 16B-aligned rows, conflict-free ldmatrix)
#define ROWB 144

#define OFF_AH   0
#define OFF_AM   (128 * ROWB)
#define OFF_BH   (2 * 128 * ROWB)
#define OFF_BM   (3 * 128 * ROWB)
#define OFF_HWW  (4 * 128 * ROWB)      // 128 f32
#define OFF_HWP  (OFF_HWW + 512)       // 2 x 128 f32 partials
#define OFF_SBV  (OFF_HWP + 1024)      // 128 x 2 f32
#define OFF_SBI  (OFF_SBV + 1024)      // 128 x 2 i32
#define OFF_KIDX (OFF_SBI + 1024)      // 128 i32
#define OFF_SRED (OFF_KIDX + 512)      // 8 doubles
#define SMEM_TOTAL (OFF_SRED + 64)

__device__ double g_loss_sum;   // zero-init; fin kernel resets after read each replay

#define LDSM4(r0, r1, r2, r3, addr) \
    asm volatile("ldmatrix.sync.aligned.m8n8.x4.shared.b16 {%0,%1,%2,%3}, [%4];" \
                 : "=r"(r0), "=r"(r1), "=r"(r2), "=r"(r3) : "r"(addr))

#define MMA(d, a, b) \
    asm volatile("mma.sync.aligned.m16n8k16.row.col.f32.f16.f16.f32 " \
                 "{%0,%1,%2,%3}, {%4,%5,%6,%7}, {%8,%9}, {%0,%1,%2,%3};" \
                 : "+f"((d)[0]), "+f"((d)[1]), "+f"((d)[2]), "+f"((d)[3]) \
                 : "r"((a)[0]), "r"((a)[1]), "r"((a)[2]), "r"((a)[3]), \
                   "r"((b)[0]), "r"((b)[1]))

__global__ void __launch_bounds__(TPB, 2)
vq_main_kernel(const float* __restrict__ x, const float* __restrict__ emb,
               float* __restrict__ out_q, float* __restrict__ out_idx, int n_rows)
{
    extern __shared__ char smem[];
    const uint32_t sb = (uint32_t)__cvta_generic_to_shared(smem);
    const int t = threadIdx.x, lane = t & 31, w = t >> 5;
    const int wm = w >> 1, wn = w & 1;       // 4 m-warps x 2 n-warps
    const int rowbase = blockIdx.x * BN;

    // ---- A split: x rows -> h (AH) + m (AM) fp16 tiles, row-major [row][k] ----
    {
        const int row = t >> 1, hseg = (t & 1) * 32;
        const bool v = (rowbase + row) < n_rows;
        const float4* xr = (const float4*)(x + (size_t)(rowbase + row) * DD + hseg);
        __half* ah = (__half*)(smem + OFF_AH) + row * LDA + hseg;
        __half* am = (__half*)(smem + OFF_AM) + row * LDA + hseg;
        #pragma unroll
        for (int j = 0; j < 8; j++) {
            float4 f = v ? xr[j] : make_float4(0.f, 0.f, 0.f, 0.f);
            float e[4] = {f.x, f.y, f.z, f.w};
            __half h[4], m[4];
            #pragma unroll
            for (int p = 0; p < 4; p++) {
                h[p] = __float2half_rn(e[p]);
                m[p] = __float2half_rn(e[p] - __half2float(h[p]));
            }
            *(__half2*)(ah + 4 * j)     = __halves2half2(h[0], h[1]);
            *(__half2*)(ah + 4 * j + 2) = __halves2half2(h[2], h[3]);
            *(__half2*)(am + 4 * j)     = __halves2half2(m[0], m[1]);
            *(__half2*)(am + 4 * j + 2) = __halves2half2(m[2], m[3]);
        }
    }

    float best[4];
    int   bk[4];
    #pragma unroll
    for (int s = 0; s < 4; s++) { best[s] = -3.402823466e38f; bk[s] = 0; }

    // ldmatrix per-lane byte offsets (within a term buffer)
    const uint32_t a_off = (uint32_t)((wm * 32 + (lane & 15)) * ROWB + (((lane >> 4) << 3) << 1));
    const uint32_t b_off = (uint32_t)((wn * 64 + (lane & 7) + ((lane >> 4) << 3)) * ROWB
                                      + ((((lane >> 3) & 1) << 3) << 1));

    #pragma unroll 1
    for (int q = 0; q < 4; q++) {
        const int qbase = q * 128;
        __syncthreads();   // previous quarter's compute done; B buffers free

        // ---- B split: codes qbase..+127 -> H (BH) + M (BM), [code][k]; partial ||w||^2 ----
        {
            const int c = t & 127, dh = (t >> 7) * 32;
            const float* ep = emb + (size_t)dh * KC + qbase + c;
            __half* bh = (__half*)(smem + OFF_BH) + c * LDA + dh;
            __half* bm = (__half*)(smem + OFF_BM) + c * LDA + dh;
            float s = 0.f;
            #pragma unroll
            for (int j = 0; j < 16; j++) {
                float e0 = __ldg(ep + (size_t)(2 * j) * KC);
                float e1 = __ldg(ep + (size_t)(2 * j + 1) * KC);
                s = fmaf(e1, e1, fmaf(e0, e0, s));
                __half h0 = __float2half_rn(e0), h1 = __float2half_rn(e1);
                __half m0 = __float2half_rn(e0 - __half2float(h0));
                __half m1 = __float2half_rn(e1 - __half2float(h1));
                *(__half2*)(bh + 2 * j) = __halves2half2(h0, h1);
                *(__half2*)(bm + 2 * j) = __halves2half2(m0, m1);
            }
            ((float*)(smem + OFF_HWP))[(t >> 7) * 128 + c] = s;
        }
        __syncthreads();
        if (t < 128) {
            const float* p = (const float*)(smem + OFF_HWP);
            ((float*)(smem + OFF_HWW))[t] = 0.5f * (p[t] + p[128 + t]);
        }
        __syncthreads();

        // ---- MMA: acc = x.w - 0.5||w||^2 via hH + mH + hM, fp32 accum ----
        float acc[2][8][4];
        {
            const float* hww = (const float*)(smem + OFF_HWW);
            #pragma unroll
            for (int nt = 0; nt < 8; nt++) {
                float2 hv = *(const float2*)(hww + wn * 64 + nt * 8 + 2 * (lane & 3));
                #pragma unroll
                for (int mt = 0; mt < 2; mt++) {
                    acc[mt][nt][0] = -hv.x; acc[mt][nt][1] = -hv.y;
                    acc[mt][nt][2] = -hv.x; acc[mt][nt][3] = -hv.y;
                }
            }
        }
        #pragma unroll
        for (int kc = 0; kc < 4; kc++) {
            const uint32_t ka = (uint32_t)(kc * 32);   // 16 fp16 = 32B per k-chunk
            uint32_t ah[2][4], am[2][4], bb[8][2];
            LDSM4(ah[0][0], ah[0][1], ah[0][2], ah[0][3], sb + OFF_AH + a_off + ka);
            LDSM4(ah[1][0], ah[1][1], ah[1][2], ah[1][3], sb + OFF_AH + a_off + ka + 16 * ROWB);
            LDSM4(am[0][0], am[0][1], am[0][2], am[0][3], sb + OFF_AM + a_off + ka);
            LDSM4(am[1][0], am[1][1], am[1][2], am[1][3], sb + OFF_AM + a_off + ka + 16 * ROWB);
            #pragma unroll
            for (int ng = 0; ng < 4; ng++)
                LDSM4(bb[2 * ng][0], bb[2 * ng][1], bb[2 * ng + 1][0], bb[2 * ng + 1][1],
                      sb + OFF_BH + b_off + ka + ng * 16 * ROWB);
            #pragma unroll
            for (int mt = 0; mt < 2; mt++)
                #pragma unroll
                for (int nt = 0; nt < 8; nt++) {
                    MMA(acc[mt][nt], ah[mt], bb[nt]);   // h.H
                    MMA(acc[mt][nt], am[mt], bb[nt]);   // m.H
                }
            #pragma unroll
            for (int ng = 0; ng < 4; ng++)
                LDSM4(bb[2 * ng][0], bb[2 * ng][1], bb[2 * ng + 1][0], bb[2 * ng + 1][1],
                      sb + OFF_BM + b_off + ka + ng * 16 * ROWB);
            #pragma unroll
            for (int mt = 0; mt < 2; mt++)
                #pragma unroll
                for (int nt = 0; nt < 8; nt++)
                    MMA(acc[mt][nt], ah[mt], bb[nt]);   // h.M
        }

        // ---- scan: strict >, ascending cols -> first-index argmin semantics ----
        #pragma unroll
        for (int mt = 0; mt < 2; mt++)
            #pragma unroll
            for (int nt = 0; nt < 8; nt++) {
                const int c0 = qbase + wn * 64 + nt * 8 + 2 * (lane & 3);
                #pragma unroll
                for (int rh = 0; rh < 2; rh++) {
                    const int s = mt * 2 + rh;
                    float v0 = acc[mt][nt][rh * 2 + 0];
                    float v1 = acc[mt][nt][rh * 2 + 1];
                    if (v0 > best[s]) { best[s] = v0; bk[s] = c0; }
                    if (v1 > best[s]) { best[s] = v1; bk[s] = c0 + 1; }
                }
            }
    }

    // ---- per-row reduce: width-4 shfl, then combine the 2 n-warps via smem ----
    #pragma unroll
    for (int s = 0; s < 4; s++) {
        float v = best[s]; int bi = bk[s];
        #pragma unroll
        for (int off = 1; off <= 2; off <<= 1) {
            float ov = __shfl_xor_sync(0xffffffffu, v, off);
            int   oi = __shfl_xor_sync(0xffffffffu, bi, off);
            if (ov > v || (ov == v && oi < bi)) { v = ov; bi = oi; }
        }
        if ((lane & 3) == 0) {
            int row = wm * 32 + (s >> 1) * 16 + (s & 1) * 8 + (lane >> 2);
            ((float*)(smem + OFF_SBV))[row * 2 + wn] = v;
            ((int*)(smem + OFF_SBI))[row * 2 + wn] = bi;
        }
    }
    __syncthreads();
    if (t < 128) {
        float v0 = ((float*)(smem + OFF_SBV))[t * 2 + 0];
        float v1 = ((float*)(smem + OFF_SBV))[t * 2 + 1];
        int   i0 = ((int*)(smem + OFF_SBI))[t * 2 + 0];
        int   i1 = ((int*)(smem + OFF_SBI))[t * 2 + 1];
        int k = (v1 > v0 || (v1 == v0 && i1 < i0)) ? i1 : i0;
        ((int*)(smem + OFF_KIDX))[t] = k;
        if (rowbase + t < n_rows) out_idx[rowbase + t] = (float)k;
    }
    __syncthreads();

    // ---- epilogue: gather winning code (L2-hot), write quantized, loss ----
    double lsum = 0.0;
    {
        const int row = t >> 1, hseg = (t & 1) * 32;
        const int grow = rowbase + row;
        if (grow < n_rows) {
            const int k = ((int*)(smem + OFF_KIDX))[row];
            const __half* ah = (const __half*)(smem + OFF_AH) + row * LDA + hseg;
            const __half* am = (const __half*)(smem + OFF_AM) + row * LDA + hseg;
            float4* qo = (float4*)(out_q + (size_t)grow * DD + hseg);
            #pragma unroll
            for (int j = 0; j < 8; j++) {
                float qv[4];
                #pragma unroll
                for (int p = 0; p < 4; p++)
                    qv[p] = __ldg(emb + (size_t)(hseg + 4 * j + p) * KC + k);
                qo[j] = make_float4(qv[0], qv[1], qv[2], qv[3]);
                float2 a0 = __half22float2(*(const __half2*)(ah + 4 * j));
                float2 a1 = __half22float2(*(const __half2*)(ah + 4 * j + 2));
                float2 b0 = __half22float2(*(const __half2*)(am + 4 * j));
                float2 b1 = __half22float2(*(const __half2*)(am + 4 * j + 2));
                float e0 = qv[0] - (a0.x + b0.x);
                float e1 = qv[1] - (a0.y + b0.y);
                float e2 = qv[2] - (a1.x + b1.x);
                float e3 = qv[3] - (a1.y + b1.y);
                lsum += (double)(e0 * e0 + e1 * e1 + e2 * e2 + e3 * e3);
            }
        }
    }

    // ---- loss reduction -> one atomic per block ----
    #pragma unroll
    for (int off = 16; off; off >>= 1) lsum += __shfl_down_sync(0xffffffffu, lsum, off);
    double* sred = (double*)(smem + OFF_SRED);
    if (lane == 0) sred[w] = lsum;
    __syncthreads();
    if (w == 0) {
        double v = (lane < 8) ? sred[lane] : 0.0;
        v += __shfl_down_sync(0xffffffffu, v, 4);
        v += __shfl_down_sync(0xffffffffu, v, 2);
        v += __shfl_down_sync(0xffffffffu, v, 1);
        if (lane == 0) atomicAdd(&g_loss_sum, v);
    }
}

__global__ void vq_fin_kernel(float* __restrict__ out_loss, double inv_count)
{
    *out_loss = (float)(1.25 * g_loss_sum * inv_count);
    g_loss_sum = 0.0;   // reset for next graph replay
}

extern "C" void kernel_launch(void* const* d_in, const int* in_sizes, int n_in,
                              void* d_out, int out_size)
{
    const float* x   = (const float*)d_in[0];   // [N, 64]
    const float* emb = (const float*)d_in[1];   // [64, 512]

    const int n_rows = in_sizes[0] / DD;
    float* out      = (float*)d_out;
    float* out_q    = out;
    float* out_idx  = out + (size_t)n_rows * DD;
    float* out_loss = out_idx + n_rows;

    cudaFuncSetAttribute(vq_main_kernel,
                         cudaFuncAttributeMaxDynamicSharedMemorySize, SMEM_TOTAL);

    int grid = (n_rows + BN - 1) / BN;   // 512

    vq_main_kernel<<<grid, TPB, SMEM_TOTAL>>>(x, emb, out_q, out_idx, n_rows);
    vq_fin_kernel<<<1, 1>>>(out_loss, 1.0 / ((double)n_rows * (double)DD));
}

// round 6
// speedup vs baseline: 2.5537x; 1.1180x over previous
#include <cuda_runtime.h>
#include <cuda_fp16.h>
#include <cstdint>

#define KC   512
#define DD   64
#define TPB  256
#define BN   128
#define LDA  72      // fp16 elems per row (144B): 16B-aligned rows, conflict-free ldmatrix
#define ROWB 144

#define OFF_AH   0
#define OFF_AM   18432
#define OFF_BH   36864
#define OFF_BM   55296
#define OFF_HWW  73728                 // 128 f32 (this quarter)
#define OFF_SBV  (OFF_HWW + 512)       // 128 x 2 f32
#define OFF_SBI  (OFF_SBV + 1024)      // 128 x 2 i32
#define OFF_KIDX (OFF_SBI + 1024)      // 128 i32
#define OFF_SRED (OFF_KIDX + 512)      // 8 doubles
#define SMEM_TOTAL (OFF_SRED + 64)

__device__ __align__(16) __half g_bh[KC * LDA];   // pre-split codebook, h-term
__device__ __align__(16) __half g_bm[KC * LDA];   // m-term
__device__ __align__(16) float  g_hww[KC];        // 0.5*||w||^2
__device__ double   g_loss_sum;                   // zero-init; last block resets
__device__ unsigned g_ctr;

#define LDSM4(r0, r1, r2, r3, addr) \
    asm volatile("ldmatrix.sync.aligned.m8n8.x4.shared.b16 {%0,%1,%2,%3}, [%4];" \
                 : "=r"(r0), "=r"(r1), "=r"(r2), "=r"(r3) : "r"(addr))

#define MMA(d, a, b) \
    asm volatile("mma.sync.aligned.m16n8k16.row.col.f32.f16.f16.f32 " \
                 "{%0,%1,%2,%3}, {%4,%5,%6,%7}, {%8,%9}, {%0,%1,%2,%3};" \
                 : "+f"((d)[0]), "+f"((d)[1]), "+f"((d)[2]), "+f"((d)[3]) \
                 : "r"((a)[0]), "r"((a)[1]), "r"((a)[2]), "r"((a)[3]), \
                   "r"((b)[0]), "r"((b)[1]))

#define CPA16(dst, src) \
    asm volatile("cp.async.cg.shared.global [%0], [%1], 16;" :: "r"(dst), "l"(src))

// ---- pre-split: emb [64][512] fp32 -> g_bh/g_bm [512][72] fp16 + g_hww ----
__global__ void __launch_bounds__(128)
vq_pre_kernel(const float* __restrict__ emb)
{
    __shared__ float sp[4][32];
    const int t = threadIdx.x;
    const int c = blockIdx.x * 32 + (t & 31);
    const int dseg = (t >> 5) * 16;

    uint32_t hw[8], mw[8];
    float s = 0.f;
    #pragma unroll
    for (int j = 0; j < 8; j++) {
        float e0 = __ldg(emb + (size_t)(dseg + 2 * j) * KC + c);
        float e1 = __ldg(emb + (size_t)(dseg + 2 * j + 1) * KC + c);
        s = fmaf(e1, e1, fmaf(e0, e0, s));
        __half h0 = __float2half_rn(e0), h1 = __float2half_rn(e1);
        __half m0 = __float2half_rn(e0 - __half2float(h0));
        __half m1 = __float2half_rn(e1 - __half2float(h1));
        hw[j] = (uint32_t)__half_as_ushort(h0) | ((uint32_t)__half_as_ushort(h1) << 16);
        mw[j] = (uint32_t)__half_as_ushort(m0) | ((uint32_t)__half_as_ushort(m1) << 16);
    }
    *(uint4*)(g_bh + c * LDA + dseg)     = make_uint4(hw[0], hw[1], hw[2], hw[3]);
    *(uint4*)(g_bh + c * LDA + dseg + 8) = make_uint4(hw[4], hw[5], hw[6], hw[7]);
    *(uint4*)(g_bm + c * LDA + dseg)     = make_uint4(mw[0], mw[1], mw[2], mw[3]);
    *(uint4*)(g_bm + c * LDA + dseg + 8) = make_uint4(mw[4], mw[5], mw[6], mw[7]);
    sp[t >> 5][t & 31] = s;
    __syncthreads();
    if (t < 32)
        g_hww[blockIdx.x * 32 + t] = 0.5f * (sp[0][t] + sp[1][t] + sp[2][t] + sp[3][t]);
}

__global__ void __launch_bounds__(TPB, 2)
vq_main_kernel(const float* __restrict__ x, float* __restrict__ out_q,
               float* __restrict__ out_idx, float* __restrict__ out_loss,
               int n_rows, double inv_count)
{
    extern __shared__ char smem[];
    const uint32_t sb = (uint32_t)__cvta_generic_to_shared(smem);
    const int t = threadIdx.x, lane = t & 31, w = t >> 5;
    const int wm = w >> 1, wn = w & 1;       // 4 m-warps x 2 n-warps
    const int rowbase = blockIdx.x * BN;

    // ---- A split: x rows -> h (AH) + m (AM) fp16 tiles, row-major [row][k] ----
    {
        const int row = t >> 1, hseg = (t & 1) * 32;
        const bool v = (rowbase + row) < n_rows;
        const float4* xr = (const float4*)(x + (size_t)(rowbase + row) * DD + hseg);
        __half* ah = (__half*)(smem + OFF_AH) + row * LDA + hseg;
        __half* am = (__half*)(smem + OFF_AM) + row * LDA + hseg;
        #pragma unroll
        for (int j = 0; j < 8; j++) {
            float4 f = v ? xr[j] : make_float4(0.f, 0.f, 0.f, 0.f);
            float e[4] = {f.x, f.y, f.z, f.w};
            __half h[4], m[4];
            #pragma unroll
            for (int p = 0; p < 4; p++) {
                h[p] = __float2half_rn(e[p]);
                m[p] = __float2half_rn(e[p] - __half2float(h[p]));
            }
            *(__half2*)(ah + 4 * j)     = __halves2half2(h[0], h[1]);
            *(__half2*)(ah + 4 * j + 2) = __halves2half2(h[2], h[3]);
            *(__half2*)(am + 4 * j)     = __halves2half2(m[0], m[1]);
            *(__half2*)(am + 4 * j + 2) = __halves2half2(m[2], m[3]);
        }
    }

    float best[4];
    int   bk[4];
    #pragma unroll
    for (int s = 0; s < 4; s++) { best[s] = -3.402823466e38f; bk[s] = 0; }

    const uint32_t a_off = (uint32_t)((wm * 32 + (lane & 15)) * ROWB + (((lane >> 4) << 3) << 1));
    const uint32_t b_off = (uint32_t)((wn * 64 + (lane & 7) + ((lane >> 4) << 3)) * ROWB
                                      + ((((lane >> 3) & 1) << 3) << 1));

    #pragma unroll 1
    for (int q = 0; q < 4; q++) {
        const int qbase = q * 128;
        __syncthreads();   // prior quarter's ldmatrix done; B buffers free (and A ready at q=0)

        // ---- bulk-copy pre-split B quarter + hww via cp.async (L2-hot, contiguous) ----
        {
            const char* srcH = (const char*)g_bh + (size_t)qbase * ROWB;
            const char* srcM = (const char*)g_bm + (size_t)qbase * ROWB;
            #pragma unroll
            for (int i = t; i < 1152; i += TPB) {     // 128*144B / 16B
                CPA16(sb + OFF_BH + i * 16, srcH + i * 16);
                CPA16(sb + OFF_BM + i * 16, srcM + i * 16);
            }
            if (t < 32) CPA16(sb + OFF_HWW + t * 16, (const char*)g_hww + qbase * 4 + t * 16);
            asm volatile("cp.async.commit_group;");
            asm volatile("cp.async.wait_group 0;" ::: "memory");
        }
        __syncthreads();

        // ---- MMA: acc = x.w - 0.5||w||^2 via hH + mH + hM, fp32 accum ----
        float acc[2][8][4];
        {
            const float* hww = (const float*)(smem + OFF_HWW);
            #pragma unroll
            for (int nt = 0; nt < 8; nt++) {
                float2 hv = *(const float2*)(hww + wn * 64 + nt * 8 + 2 * (lane & 3));
                #pragma unroll
                for (int mt = 0; mt < 2; mt++) {
                    acc[mt][nt][0] = -hv.x; acc[mt][nt][1] = -hv.y;
                    acc[mt][nt][2] = -hv.x; acc[mt][nt][3] = -hv.y;
                }
            }
        }
        #pragma unroll
        for (int kc = 0; kc < 4; kc++) {
            const uint32_t ka = (uint32_t)(kc * 32);
            uint32_t ah[2][4], am[2][4], bb[8][2];
            LDSM4(ah[0][0], ah[0][1], ah[0][2], ah[0][3], sb + OFF_AH + a_off + ka);
            LDSM4(ah[1][0], ah[1][1], ah[1][2], ah[1][3], sb + OFF_AH + a_off + ka + 16 * ROWB);
            LDSM4(am[0][0], am[0][1], am[0][2], am[0][3], sb + OFF_AM + a_off + ka);
            LDSM4(am[1][0], am[1][1], am[1][2], am[1][3], sb + OFF_AM + a_off + ka + 16 * ROWB);
            #pragma unroll
            for (int ng = 0; ng < 4; ng++)
                LDSM4(bb[2 * ng][0], bb[2 * ng][1], bb[2 * ng + 1][0], bb[2 * ng + 1][1],
                      sb + OFF_BH + b_off + ka + ng * 16 * ROWB);
            #pragma unroll
            for (int mt = 0; mt < 2; mt++)
                #pragma unroll
                for (int nt = 0; nt < 8; nt++) {
                    MMA(acc[mt][nt], ah[mt], bb[nt]);   // h.H
                    MMA(acc[mt][nt], am[mt], bb[nt]);   // m.H
                }
            #pragma unroll
            for (int ng = 0; ng < 4; ng++)
                LDSM4(bb[2 * ng][0], bb[2 * ng][1], bb[2 * ng + 1][0], bb[2 * ng + 1][1],
                      sb + OFF_BM + b_off + ka + ng * 16 * ROWB);
            #pragma unroll
            for (int mt = 0; mt < 2; mt++)
                #pragma unroll
                for (int nt = 0; nt < 8; nt++)
                    MMA(acc[mt][nt], ah[mt], bb[nt]);   // h.M
        }

        // ---- scan: strict >, ascending cols -> first-index argmin semantics ----
        #pragma unroll
        for (int mt = 0; mt < 2; mt++)
            #pragma unroll
            for (int nt = 0; nt < 8; nt++) {
                const int c0 = qbase + wn * 64 + nt * 8 + 2 * (lane & 3);
                #pragma unroll
                for (int rh = 0; rh < 2; rh++) {
                    const int s = mt * 2 + rh;
                    float v0 = acc[mt][nt][rh * 2 + 0];
                    float v1 = acc[mt][nt][rh * 2 + 1];
                    if (v0 > best[s]) { best[s] = v0; bk[s] = c0; }
                    if (v1 > best[s]) { best[s] = v1; bk[s] = c0 + 1; }
                }
            }
    }

    // ---- per-row reduce: width-4 shfl, then combine the 2 n-warps ----
    #pragma unroll
    for (int s = 0; s < 4; s++) {
        float v = best[s]; int bi = bk[s];
        #pragma unroll
        for (int off = 1; off <= 2; off <<= 1) {
            float ov = __shfl_xor_sync(0xffffffffu, v, off);
            int   oi = __shfl_xor_sync(0xffffffffu, bi, off);
            if (ov > v || (ov == v && oi < bi)) { v = ov; bi = oi; }
        }
        if ((lane & 3) == 0) {
            int row = wm * 32 + (s >> 1) * 16 + (s & 1) * 8 + (lane >> 2);
            ((float*)(smem + OFF_SBV))[row * 2 + wn] = v;
            ((int*)(smem + OFF_SBI))[row * 2 + wn] = bi;
        }
    }
    __syncthreads();
    if (t < 128) {
        float v0 = ((float*)(smem + OFF_SBV))[t * 2 + 0];
        float v1 = ((float*)(smem + OFF_SBV))[t * 2 + 1];
        int   i0 = ((int*)(smem + OFF_SBI))[t * 2 + 0];
        int   i1 = ((int*)(smem + OFF_SBI))[t * 2 + 1];
        int k = (v1 > v0 || (v1 == v0 && i1 < i0)) ? i1 : i0;
        ((int*)(smem + OFF_KIDX))[t] = k;
        if (rowbase + t < n_rows) out_idx[rowbase + t] = (float)k;
    }
    __syncthreads();

    // ---- epilogue: q = h+m from pre-split (contiguous 144B gather), loss ----
    double lsum = 0.0;
    {
        const int row = t >> 1, hseg = (t & 1) * 32;
        const int grow = rowbase + row;
        if (grow < n_rows) {
            const int k = ((int*)(smem + OFF_KIDX))[row];
            const __half* gh = g_bh + (size_t)k * LDA + hseg;
            const __half* gm = g_bm + (size_t)k * LDA + hseg;
            const __half* ah = (const __half*)(smem + OFF_AH) + row * LDA + hseg;
            const __half* am = (const __half*)(smem + OFF_AM) + row * LDA + hseg;
            float4* qo = (float4*)(out_q + (size_t)grow * DD + hseg);
            #pragma unroll
            for (int j = 0; j < 8; j++) {
                float2 wh0 = __half22float2(*(const __half2*)(gh + 4 * j));
                float2 wh1 = __half22float2(*(const __half2*)(gh + 4 * j + 2));
                float2 wm0 = __half22float2(*(const __half2*)(gm + 4 * j));
                float2 wm1 = __half22float2(*(const __half2*)(gm + 4 * j + 2));
                float q0 = wh0.x + wm0.x, q1 = wh0.y + wm0.y;
                float q2 = wh1.x + wm1.x, q3 = wh1.y + wm1.y;
                qo[j] = make_float4(q0, q1, q2, q3);
                float2 a0 = __half22float2(*(const __half2*)(ah + 4 * j));
                float2 a1 = __half22float2(*(const __half2*)(ah + 4 * j + 2));
                float2 b0 = __half22float2(*(const __half2*)(am + 4 * j));
                float2 b1 = __half22float2(*(const __half2*)(am + 4 * j + 2));
                float e0 = q0 - (a0.x + b0.x);
                float e1 = q1 - (a0.y + b0.y);
                float e2 = q2 - (a1.x + b1.x);
                float e3 = q3 - (a1.y + b1.y);
                lsum += (double)(e0 * e0 + e1 * e1 + e2 * e2 + e3 * e3);
            }
        }
    }

    // ---- loss reduction -> atomic; last block finalizes + resets ----
    #pragma unroll
    for (int off = 16; off; off >>= 1) lsum += __shfl_down_sync(0xffffffffu, lsum, off);
    double* sred = (double*)(smem + OFF_SRED);
    if (lane == 0) sred[w] = lsum;
    __syncthreads();
    if (w == 0) {
        double v = (lane < 8) ? sred[lane] : 0.0;
        v += __shfl_down_sync(0xffffffffu, v, 4);
        v += __shfl_down_sync(0xffffffffu, v, 2);
        v += __shfl_down_sync(0xffffffffu, v, 1);
        if (lane == 0) {
            atomicAdd(&g_loss_sum, v);
            __threadfence();
            unsigned prev = atomicAdd(&g_ctr, 1u);
            if (prev == gridDim.x - 1) {
                __threadfence();
                double total = atomicAdd(&g_loss_sum, 0.0);
                *out_loss = (float)(1.25 * total * inv_count);
                g_loss_sum = 0.0;   // reset for next graph replay
                g_ctr = 0u;
            }
        }
    }
}

extern "C" void kernel_launch(void* const* d_in, const int* in_sizes, int n_in,
                              void* d_out, int out_size)
{
    const float* x   = (const float*)d_in[0];   // [N, 64]
    const float* emb = (const float*)d_in[1];   // [64, 512]

    const int n_rows = in_sizes[0] / DD;
    float* out      = (float*)d_out;
    float* out_q    = out;
    float* out_idx  = out + (size_t)n_rows * DD;
    float* out_loss = out_idx + n_rows;

    cudaFuncSetAttribute(vq_main_kernel,
                         cudaFuncAttributeMaxDynamicSharedMemorySize, SMEM_TOTAL);

    int grid = (n_rows + BN - 1) / BN;   // 512

    vq_pre_kernel<<<16, 128>>>(emb);
    vq_main_kernel<<<grid, TPB, SMEM_TOTAL>>>(x, out_q, out_idx, out_loss,
                                              n_rows, 1.0 / ((double)n_rows * (double)DD));
}